// round 7
// baseline (speedup 1.0000x reference)
#include <cuda_runtime.h>
#include <math_constants.h>

#define NB 8
#define NPTS 4096
#define KNN 16
#define MPTS (NB * NPTS)
#define CH 32
#define NCLS 40
#define NCHUNK (NPTS / 32)   // 128 chunks of 32 per batch

__device__ float4 g_p4[MPTS];
__device__ float4 g_sp4[MPTS];   // norm-sorted points per batch
__device__ int    g_sidx[MPTS];  // sorted pos -> original batch-local idx
__device__ int    g_knn[MPTS * KNN];
__device__ float  g_y[MPTS * CH];
__device__ float  g_pool[NB * CH];

__device__ __forceinline__ float safe_norm3(float x, float y, float z) {
    float s = x * x + y * y + z * z;
    return s > 0.f ? sqrtf(s) : 0.f;
}

__device__ __forceinline__ float angle3(float ax, float ay, float az,
                                        float bx, float by, float bz) {
    float cx = ay * bz - az * by;
    float cy = az * bx - ax * bz;
    float cz = ax * by - ay * bx;
    float cn = safe_norm3(cx, cy, cz);
    float d  = ax * bx + ay * by + az * bz;
    bool ok = (cn > 0.f) || (d != 0.f);
    return ok ? atan2f(cn, d) : 0.f;
}

// pos -> (x,y,z,|p|^2)
__global__ __launch_bounds__(256) void prep_kernel(const float* __restrict__ pos) {
    int i = blockIdx.x * 256 + threadIdx.x;
    float x = pos[3 * i + 0], y = pos[3 * i + 1], z = pos[3 * i + 2];
    g_p4[i] = make_float4(x, y, z, x * x + y * y + z * z);
}

// per-batch bitonic sort by |p|^2 (key packs w-bits | idx for determinism)
__global__ __launch_bounds__(512) void sort_kernel() {
    __shared__ unsigned long long sk[NPTS];
    int b   = blockIdx.x;
    int tid = threadIdx.x;
    int boff = b * NPTS;

    for (int i = tid; i < NPTS; i += 512) {
        float w = g_p4[boff + i].w;   // w >= 0 -> uint order == float order
        sk[i] = ((unsigned long long)__float_as_uint(w) << 32) | (unsigned)i;
    }
    __syncthreads();

    for (int k = 2; k <= NPTS; k <<= 1) {
        for (int j = k >> 1; j > 0; j >>= 1) {
            for (int i = tid; i < NPTS; i += 512) {
                int ixj = i ^ j;
                if (ixj > i) {
                    bool up = (i & k) == 0;
                    unsigned long long a = sk[i], c = sk[ixj];
                    if ((a > c) == up) { sk[i] = c; sk[ixj] = a; }
                }
            }
            __syncthreads();
        }
    }

    for (int i = tid; i < NPTS; i += 512) {
        int o = (int)(sk[i] & 0xFFFu);
        g_sidx[boff + i] = o;
        g_sp4[boff + i] = g_p4[boff + o];
    }
}

__global__ void pool_init_kernel() {
    int t = threadIdx.x;
    if (t < NB * CH) g_pool[t] = 0.f;
}

// ---------------------------------------------------------------------------
// kNN v4: norm-banded exact search. 2 queries/warp (adjacent in sorted order);
// chunks of 32 candidates expand outward from the query's norm rank; a side is
// pruned (exactly, with fp safety margin) once (|c|-|q|)^2 exceeds the running
// 16th-best real distance for BOTH queries. Selection machinery = proven v3.
// ---------------------------------------------------------------------------
__global__ __launch_bounds__(256) void knn_kernel() {
    const unsigned FULL = 0xFFFFFFFFu;
    const float INF = CUDART_INF_F;
    int lane = threadIdx.x & 31;
    int warp = threadIdx.x >> 5;
    int half = lane >> 4;
    int lh   = lane & 15;
    int hsh  = half << 4;

    int batch = blockIdx.x >> 8;
    int boff  = batch * NPTS;
    int rs0   = (blockIdx.x & 255) * 16 + warp * 2;   // sorted pos (even)

    float4 p0 = g_sp4[boff + rs0];
    float4 p1 = g_sp4[boff + rs0 + 1];
    float m2x0 = -2.f * p0.x, m2y0 = -2.f * p0.y, m2z0 = -2.f * p0.z;
    float m2x1 = -2.f * p1.x, m2y1 = -2.f * p1.y, m2z1 = -2.f * p1.z;
    float wq0 = p0.w, wq1 = p1.w;
    float nq0 = sqrtf(wq0), nq1 = sqrtf(wq1);

    float L  = INF;      // my slot of my query's sorted top-16 (shifted d2)
    int   LI = 0;        // sorted position of that candidate
    float tp0 = INF;     // q0 running 16th best (shifted: real = tp + wq)
    float tp1 = INF;

    int chunkC = rs0 >> 5;
    int pr = chunkC, pl = chunkC - 1;
    bool rdone = false, ldone = (pl < 0);
    bool preferR = true;

    while (!(rdone && ldone)) {
        bool pickR = rdone ? false : (ldone ? true : preferR);
        preferR = !pickR;
        int p = pickR ? pr : pl;

        // exact prune test for this side (conservative fp margin)
        if (pickR) {
            float s = sqrtf(g_sp4[boff + p * 32].w);       // min norm in chunk
            float b0 = s - nq0, b1 = s - nq1;
            bool x0 = (b0 > 0.f) && (b0 * b0 > (tp0 + wq0) * 1.0002f);
            bool x1 = (b1 > 0.f) && (b1 * b1 > (tp1 + wq1) * 1.0002f);
            if (x0 && x1) { rdone = true; continue; }
        } else {
            float s = sqrtf(g_sp4[boff + p * 32 + 31].w);  // max norm in chunk
            float b0 = nq0 - s, b1 = nq1 - s;
            bool x0 = (b0 > 0.f) && (b0 * b0 > (tp0 + wq0) * 1.0002f);
            bool x1 = (b1 > 0.f) && (b1 * b1 > (tp1 + wq1) * 1.0002f);
            if (x0 && x1) { ldone = true; continue; }
        }

        int cbase = p * 32;
        float4 c = g_sp4[boff + cbase + lane];
        float d0 = fmaf(c.x, m2x0, fmaf(c.y, m2y0, fmaf(c.z, m2z0, c.w)));
        float d1 = fmaf(c.x, m2x1, fmaf(c.y, m2y1, fmaf(c.z, m2z1, c.w)));
        if (p == chunkC) {                   // self exclusion (uniform branch)
            int cl = cbase + lane;
            if (cl == rs0)     d0 = INF;
            if (cl == rs0 + 1) d1 = INF;
        }
        unsigned bal0 = __ballot_sync(FULL, d0 < tp0);
        unsigned bal1 = __ballot_sync(FULL, d1 < tp1);
        while (bal0 | bal1) {
            int s0 = __ffs(bal0) - 1;
            int s1 = __ffs(bal1) - 1;
            float v0 = __shfl_sync(FULL, d0, bal0 ? s0 : 0);
            float v1 = __shfl_sync(FULL, d1, bal1 ? s1 : 0);
            float v;
            int   vi;
            if (half) { v = bal1 ? v1 : INF; vi = cbase + s1; }
            else      { v = bal0 ? v0 : INF; vi = cbase + s0; }
            unsigned ble = __ballot_sync(FULL, L <= v);
            int pos = __popc((ble >> hsh) & 0xFFFFu);
            float Lup = __shfl_up_sync(FULL, L, 1);
            int  LIup = __shfl_up_sync(FULL, LI, 1);
            if (lh == pos)      { L = v;   LI = vi;   }
            else if (lh > pos)  { L = Lup; LI = LIup; }
            tp0 = __shfl_sync(FULL, L, 15);
            tp1 = __shfl_sync(FULL, L, 31);
            bal0 &= bal0 - 1;
            bal1 &= bal1 - 1;
        }

        if (pickR) { pr++; if (pr >= NCHUNK) rdone = true; }
        else       { pl--; if (pl < 0)       ldone = true; }
    }

    int rs    = rs0 + half;
    int qorig = g_sidx[boff + rs];
    int nbr   = g_sidx[boff + LI];
    g_knn[(boff + qorig) * KNN + lh] = boff + nbr;
}

// ---------------------------------------------------------------------------
// conv1 (+ fused y = w2a[0:32]^T x1 + b2a)
// ---------------------------------------------------------------------------
__global__ __launch_bounds__(256) void conv1_kernel(
    const float* __restrict__ pos, const float* __restrict__ nrm,
    const float* __restrict__ w1a, const float* __restrict__ b1a,
    const float* __restrict__ w1b, const float* __restrict__ b1b,
    const float* __restrict__ w2a, const float* __restrict__ b2a)
{
    __shared__ float4 sf[8][20];
    __shared__ float  sh[8][17][32];
    int warp = threadIdx.x >> 5;
    int lane = threadIdx.x & 31;
    int i    = blockIdx.x * 8 + warp;

    float wa0 = w1a[0 * 32 + lane], wa1 = w1a[1 * 32 + lane];
    float wa2 = w1a[2 * 32 + lane], wa3 = w1a[3 * 32 + lane];
    float ba  = b1a[lane];
    float wb[32];
#pragma unroll
    for (int k = 0; k < 32; k++) wb[k] = w1b[k * 32 + lane];
    float bb = b1b[lane];

    float pix = pos[3 * i + 0], piy = pos[3 * i + 1], piz = pos[3 * i + 2];
    float nix = nrm[3 * i + 0], niy = nrm[3 * i + 1], niz = nrm[3 * i + 2];

    int j = (lane < KNN) ? g_knn[i * KNN + lane] : i;   // lane16 = self loop
    float pjx = pos[3 * j + 0], pjy = pos[3 * j + 1], pjz = pos[3 * j + 2];
    float njx = nrm[3 * j + 0], njy = nrm[3 * j + 1], njz = nrm[3 * j + 2];

    float px = pjx - pix, py = pjy - piy, pz = pjz - piz;
    float f0 = safe_norm3(px, py, pz);
    float f1 = angle3(nix, niy, niz, px, py, pz);
    float f2 = angle3(njx, njy, njz, px, py, pz);
    float f3 = angle3(nix, niy, niz, njx, njy, njz);
    if (lane < 17) sf[warp][lane] = make_float4(f0, f1, f2, f3);
    __syncwarp();

    for (int e = 0; e < 17; e++) {
        float4 f = sf[warp][e];
        float h = ba;
        h = fmaf(f.x, wa0, h); h = fmaf(f.y, wa1, h);
        h = fmaf(f.z, wa2, h); h = fmaf(f.w, wa3, h);
        sh[warp][e][lane] = fmaxf(h, 0.f);
    }
    __syncwarp();

    float best = -CUDART_INF_F;
    for (int e = 0; e < 17; e++) {
        float o0 = bb, o1 = 0.f, o2 = 0.f, o3 = 0.f;
        const float4* hv4 = (const float4*)sh[warp][e];
#pragma unroll
        for (int m = 0; m < 8; m++) {
            float4 hv = hv4[m];
            o0 = fmaf(hv.x, wb[4 * m + 0], o0);
            o1 = fmaf(hv.y, wb[4 * m + 1], o1);
            o2 = fmaf(hv.z, wb[4 * m + 2], o2);
            o3 = fmaf(hv.w, wb[4 * m + 3], o3);
        }
        best = fmaxf(best, (o0 + o1) + (o2 + o3));
    }
    float x1v = fmaxf(best, 0.f);

    sh[warp][0][lane] = x1v;
    __syncwarp();
    float w2[32];
#pragma unroll
    for (int k = 0; k < 32; k++) w2[k] = w2a[k * 32 + lane];
    float a0 = b2a[lane], a1 = 0.f, a2 = 0.f, a3 = 0.f;
    const float4* xv4 = (const float4*)sh[warp][0];
#pragma unroll
    for (int m = 0; m < 8; m++) {
        float4 xv = xv4[m];
        a0 = fmaf(xv.x, w2[4 * m + 0], a0);
        a1 = fmaf(xv.y, w2[4 * m + 1], a1);
        a2 = fmaf(xv.z, w2[4 * m + 2], a2);
        a3 = fmaf(xv.w, w2[4 * m + 3], a3);
    }
    g_y[i * CH + lane] = (a0 + a1) + (a2 + a3);
}

// ---------------------------------------------------------------------------
// conv2 (+ fused global max pool)
// ---------------------------------------------------------------------------
__global__ __launch_bounds__(256) void conv2_kernel(
    const float* __restrict__ pos, const float* __restrict__ nrm,
    const float* __restrict__ w2a,
    const float* __restrict__ w2b, const float* __restrict__ b2b)
{
    __shared__ float4 sf[8][20];
    __shared__ int    si[8][20];
    __shared__ float  sh[8][17][32];
    __shared__ float  red[8][32];
    int warp = threadIdx.x >> 5;
    int lane = threadIdx.x & 31;
    int i    = blockIdx.x * 8 + warp;

    float wa32 = w2a[32 * 32 + lane], wa33 = w2a[33 * 32 + lane];
    float wa34 = w2a[34 * 32 + lane], wa35 = w2a[35 * 32 + lane];
    float wb[32];
#pragma unroll
    for (int k = 0; k < 32; k++) wb[k] = w2b[k * 32 + lane];
    float bb = b2b[lane];

    float pix = pos[3 * i + 0], piy = pos[3 * i + 1], piz = pos[3 * i + 2];
    float nix = nrm[3 * i + 0], niy = nrm[3 * i + 1], niz = nrm[3 * i + 2];

    int j = (lane < KNN) ? g_knn[i * KNN + lane] : i;
    float pjx = pos[3 * j + 0], pjy = pos[3 * j + 1], pjz = pos[3 * j + 2];
    float njx = nrm[3 * j + 0], njy = nrm[3 * j + 1], njz = nrm[3 * j + 2];

    float px = pjx - pix, py = pjy - piy, pz = pjz - piz;
    float f0 = safe_norm3(px, py, pz);
    float f1 = angle3(nix, niy, niz, px, py, pz);
    float f2 = angle3(njx, njy, njz, px, py, pz);
    float f3 = angle3(nix, niy, niz, njx, njy, njz);
    if (lane < 17) { sf[warp][lane] = make_float4(f0, f1, f2, f3); si[warp][lane] = j; }
    __syncwarp();

    float yv[17];
#pragma unroll
    for (int e = 0; e < 17; e++)
        yv[e] = g_y[si[warp][e] * CH + lane];

#pragma unroll
    for (int e = 0; e < 17; e++) {
        float4 f = sf[warp][e];
        float h = yv[e];
        h = fmaf(f.x, wa32, h); h = fmaf(f.y, wa33, h);
        h = fmaf(f.z, wa34, h); h = fmaf(f.w, wa35, h);
        sh[warp][e][lane] = fmaxf(h, 0.f);
    }
    __syncwarp();

    float best = -CUDART_INF_F;
    for (int e = 0; e < 17; e++) {
        float o0 = bb, o1 = 0.f, o2 = 0.f, o3 = 0.f;
        const float4* hv4 = (const float4*)sh[warp][e];
#pragma unroll
        for (int m = 0; m < 8; m++) {
            float4 hv = hv4[m];
            o0 = fmaf(hv.x, wb[4 * m + 0], o0);
            o1 = fmaf(hv.y, wb[4 * m + 1], o1);
            o2 = fmaf(hv.z, wb[4 * m + 2], o2);
            o3 = fmaf(hv.w, wb[4 * m + 3], o3);
        }
        best = fmaxf(best, (o0 + o1) + (o2 + o3));
    }
    red[warp][lane] = fmaxf(best, 0.f);
    __syncthreads();

    if (warp == 0) {
        float m = red[0][lane];
#pragma unroll
        for (int r = 1; r < 8; r++) m = fmaxf(m, red[r][lane]);
        int b = (blockIdx.x * 8) >> 12;
        atomicMax((int*)&g_pool[b * CH + lane], __float_as_int(m));
    }
}

__global__ void fc_kernel(const float* __restrict__ wc,
                          const float* __restrict__ bc,
                          float* __restrict__ out) {
    int t = threadIdx.x;
    if (t < NB * NCLS) {
        int b = t / NCLS, o = t % NCLS;
        float acc = bc[o];
#pragma unroll
        for (int c = 0; c < CH; c++)
            acc = fmaf(g_pool[b * CH + c], wc[c * NCLS + o], acc);
        out[t] = acc;
    }
}

extern "C" void kernel_launch(void* const* d_in, const int* in_sizes, int n_in,
                              void* d_out, int out_size) {
    const float* pos = (const float*)d_in[0];
    const float* nrm = (const float*)d_in[1];
    const float* w1a = (const float*)d_in[3];
    const float* b1a = (const float*)d_in[4];
    const float* w1b = (const float*)d_in[5];
    const float* b1b = (const float*)d_in[6];
    const float* w2a = (const float*)d_in[7];
    const float* b2a = (const float*)d_in[8];
    const float* w2b = (const float*)d_in[9];
    const float* b2b = (const float*)d_in[10];
    const float* wc  = (const float*)d_in[11];
    const float* bc  = (const float*)d_in[12];
    float* out = (float*)d_out;

    prep_kernel<<<MPTS / 256, 256>>>(pos);     // 1
    sort_kernel<<<NB, 512>>>();                // 2
    pool_init_kernel<<<1, 256>>>();            // 3
    knn_kernel<<<MPTS / 16, 256>>>();          // 4 (ncu sample slot)
    conv1_kernel<<<MPTS / 8, 256>>>(pos, nrm, w1a, b1a, w1b, b1b, w2a, b2a);
    conv2_kernel<<<MPTS / 8, 256>>>(pos, nrm, w2a, w2b, b2b);
    fc_kernel<<<1, 320>>>(wc, bc, out);
}

// round 8
// speedup vs baseline: 1.0128x; 1.0128x over previous
#include <cuda_runtime.h>
#include <math_constants.h>

#define NB 8
#define NPTS 4096
#define KNN 16
#define MPTS (NB * NPTS)
#define CH 32
#define NCLS 40

__device__ float4 g_p4[MPTS];
__device__ int    g_knn[MPTS * KNN];
__device__ float  g_y[MPTS * CH];
__device__ float  g_pool[NB * CH];

__device__ __forceinline__ float safe_norm3(float x, float y, float z) {
    float s = x * x + y * y + z * z;
    return s > 0.f ? sqrtf(s) : 0.f;
}

__device__ __forceinline__ float angle3(float ax, float ay, float az,
                                        float bx, float by, float bz) {
    float cx = ay * bz - az * by;
    float cy = az * bx - ax * bz;
    float cz = ax * by - ay * bx;
    float cn = safe_norm3(cx, cy, cz);
    float d  = ax * bx + ay * by + az * bz;
    bool ok = (cn > 0.f) || (d != 0.f);
    return ok ? atan2f(cn, d) : 0.f;
}

// pos -> (x,y,z,|p|^2); split so knn is the 4th launch (ncu sample slot)
__global__ __launch_bounds__(256) void prep_kernel(const float* __restrict__ pos,
                                                   int base) {
    int i = base + blockIdx.x * 256 + threadIdx.x;
    float x = pos[3 * i + 0], y = pos[3 * i + 1], z = pos[3 * i + 2];
    g_p4[i] = make_float4(x, y, z, x * x + y * y + z * z);
}

__global__ void pool_init_kernel() {
    int t = threadIdx.x;
    if (t < NB * CH) g_pool[t] = 0.f;
}

// ---------------------------------------------------------------------------
// kNN warp-select v5: 2 queries/warp; each iteration covers 64 candidates via
// fmin-paired distances, so the common (no-hit) path spends one ballot pair
// per 64 candidates. On a hit, expand into exact per-candidate masks and run
// the proven sorted-insert machinery (stale inserts are self-neutralizing).
// ---------------------------------------------------------------------------
__global__ __launch_bounds__(256) void knn_kernel() {
    const unsigned FULL = 0xFFFFFFFFu;
    const float INF = CUDART_INF_F;
    int lane = threadIdx.x & 31;
    int warp = threadIdx.x >> 5;
    int half = lane >> 4;
    int lh   = lane & 15;
    int hsh  = half << 4;

    int qbase = blockIdx.x * 16;
    int q0    = qbase + warp * 2;          // even
    int batch = blockIdx.x >> 8;
    int q0l   = q0 & (NPTS - 1);
    int q1l   = q0l + 1;
    int selfb = q0l & ~63;                 // 64-block holding both queries

    float4 p0 = g_p4[q0];
    float4 p1 = g_p4[q0 + 1];
    float m2x0 = -2.f * p0.x, m2y0 = -2.f * p0.y, m2z0 = -2.f * p0.z;
    float m2x1 = -2.f * p1.x, m2y1 = -2.f * p1.y, m2z1 = -2.f * p1.z;

    float L  = INF;      // my slot of my query's sorted top-16 (shifted d2)
    int   LI = 0;
    float tp0 = INF;     // q0's running 16th best
    float tp1 = INF;

    const float4* bp = g_p4 + batch * NPTS;
    __shared__ float4 tile[1024];

    for (int t = 0; t < NPTS; t += 1024) {
        __syncthreads();
#pragma unroll
        for (int u = 0; u < 4; u++)
            tile[threadIdx.x + u * 256] = bp[t + threadIdx.x + u * 256];
        __syncthreads();

#pragma unroll 2
        for (int s = 0; s < 16; s++) {
            int base = t + s * 64;
            float4 ca = tile[s * 64 + lane];
            float4 cb = tile[s * 64 + 32 + lane];
            float d0a = fmaf(ca.x, m2x0, fmaf(ca.y, m2y0, fmaf(ca.z, m2z0, ca.w)));
            float d1a = fmaf(ca.x, m2x1, fmaf(ca.y, m2y1, fmaf(ca.z, m2z1, ca.w)));
            float d0b = fmaf(cb.x, m2x0, fmaf(cb.y, m2y0, fmaf(cb.z, m2z0, cb.w)));
            float d1b = fmaf(cb.x, m2x1, fmaf(cb.y, m2y1, fmaf(cb.z, m2z1, cb.w)));
            if (base == selfb) {           // rare uniform branch
                int cla = base + lane, clb = base + 32 + lane;
                if (cla == q0l) d0a = INF;
                if (clb == q0l) d0b = INF;
                if (cla == q1l) d1a = INF;
                if (clb == q1l) d1b = INF;
            }
            float e0 = fminf(d0a, d0b);
            float e1 = fminf(d1a, d1b);
            unsigned h0 = __ballot_sync(FULL, e0 < tp0);
            unsigned h1 = __ballot_sync(FULL, e1 < tp1);
            if (h0 | h1) {
                unsigned m0a = __ballot_sync(FULL, d0a < tp0);
                unsigned m0b = __ballot_sync(FULL, d0b < tp0);
                unsigned m1a = __ballot_sync(FULL, d1a < tp1);
                unsigned m1b = __ballot_sync(FULL, d1b < tp1);
                while (m0a | m0b | m1a | m1b) {
                    // q0 pick (a-slots first: lower candidate indices)
                    bool a0 = (m0a != 0);
                    unsigned mm0 = a0 ? m0a : m0b;
                    int s0 = __ffs(mm0) - 1;
                    float v0 = __shfl_sync(FULL, a0 ? d0a : d0b, mm0 ? s0 : 0);
                    int  vi0 = base + (a0 ? 0 : 32) + s0;
                    if (!mm0) v0 = INF;
                    // q1 pick
                    bool a1 = (m1a != 0);
                    unsigned mm1 = a1 ? m1a : m1b;
                    int s1 = __ffs(mm1) - 1;
                    float v1 = __shfl_sync(FULL, a1 ? d1a : d1b, mm1 ? s1 : 0);
                    int  vi1 = base + (a1 ? 0 : 32) + s1;
                    if (!mm1) v1 = INF;

                    float v  = half ? v1 : v0;
                    int   vi = half ? vi1 : vi0;
                    unsigned ble = __ballot_sync(FULL, L <= v);
                    int pos = __popc((ble >> hsh) & 0xFFFFu);
                    float Lup = __shfl_up_sync(FULL, L, 1);
                    int  LIup = __shfl_up_sync(FULL, LI, 1);
                    if (lh == pos)      { L = v;   LI = vi;   }
                    else if (lh > pos)  { L = Lup; LI = LIup; }
                    tp0 = __shfl_sync(FULL, L, 15);
                    tp1 = __shfl_sync(FULL, L, 31);
                    if (a0) m0a &= m0a - 1; else m0b &= m0b - 1;
                    if (a1) m1a &= m1a - 1; else m1b &= m1b - 1;
                }
            }
        }
    }
    int q = q0 + half;
    g_knn[q * KNN + lh] = batch * NPTS + LI;
}

// ---------------------------------------------------------------------------
// conv1 (+ fused y = w2a[0:32]^T x1 + b2a)
// ---------------------------------------------------------------------------
__global__ __launch_bounds__(256) void conv1_kernel(
    const float* __restrict__ pos, const float* __restrict__ nrm,
    const float* __restrict__ w1a, const float* __restrict__ b1a,
    const float* __restrict__ w1b, const float* __restrict__ b1b,
    const float* __restrict__ w2a, const float* __restrict__ b2a)
{
    __shared__ float4 sf[8][20];
    __shared__ float  sh[8][17][32];
    int warp = threadIdx.x >> 5;
    int lane = threadIdx.x & 31;
    int i    = blockIdx.x * 8 + warp;

    float wa0 = w1a[0 * 32 + lane], wa1 = w1a[1 * 32 + lane];
    float wa2 = w1a[2 * 32 + lane], wa3 = w1a[3 * 32 + lane];
    float ba  = b1a[lane];
    float wb[32];
#pragma unroll
    for (int k = 0; k < 32; k++) wb[k] = w1b[k * 32 + lane];
    float bb = b1b[lane];

    float pix = pos[3 * i + 0], piy = pos[3 * i + 1], piz = pos[3 * i + 2];
    float nix = nrm[3 * i + 0], niy = nrm[3 * i + 1], niz = nrm[3 * i + 2];

    int j = (lane < KNN) ? g_knn[i * KNN + lane] : i;   // lane16 = self loop
    float pjx = pos[3 * j + 0], pjy = pos[3 * j + 1], pjz = pos[3 * j + 2];
    float njx = nrm[3 * j + 0], njy = nrm[3 * j + 1], njz = nrm[3 * j + 2];

    float px = pjx - pix, py = pjy - piy, pz = pjz - piz;
    float f0 = safe_norm3(px, py, pz);
    float f1 = angle3(nix, niy, niz, px, py, pz);
    float f2 = angle3(njx, njy, njz, px, py, pz);
    float f3 = angle3(nix, niy, niz, njx, njy, njz);
    if (lane < 17) sf[warp][lane] = make_float4(f0, f1, f2, f3);
    __syncwarp();

    for (int e = 0; e < 17; e++) {
        float4 f = sf[warp][e];
        float h = ba;
        h = fmaf(f.x, wa0, h); h = fmaf(f.y, wa1, h);
        h = fmaf(f.z, wa2, h); h = fmaf(f.w, wa3, h);
        sh[warp][e][lane] = fmaxf(h, 0.f);
    }
    __syncwarp();

    float best = -CUDART_INF_F;
    for (int e = 0; e < 17; e++) {
        float o0 = bb, o1 = 0.f, o2 = 0.f, o3 = 0.f;
        const float4* hv4 = (const float4*)sh[warp][e];
#pragma unroll
        for (int m = 0; m < 8; m++) {
            float4 hv = hv4[m];
            o0 = fmaf(hv.x, wb[4 * m + 0], o0);
            o1 = fmaf(hv.y, wb[4 * m + 1], o1);
            o2 = fmaf(hv.z, wb[4 * m + 2], o2);
            o3 = fmaf(hv.w, wb[4 * m + 3], o3);
        }
        best = fmaxf(best, (o0 + o1) + (o2 + o3));
    }
    float x1v = fmaxf(best, 0.f);

    sh[warp][0][lane] = x1v;
    __syncwarp();
    float w2[32];
#pragma unroll
    for (int k = 0; k < 32; k++) w2[k] = w2a[k * 32 + lane];
    float a0 = b2a[lane], a1 = 0.f, a2 = 0.f, a3 = 0.f;
    const float4* xv4 = (const float4*)sh[warp][0];
#pragma unroll
    for (int m = 0; m < 8; m++) {
        float4 xv = xv4[m];
        a0 = fmaf(xv.x, w2[4 * m + 0], a0);
        a1 = fmaf(xv.y, w2[4 * m + 1], a1);
        a2 = fmaf(xv.z, w2[4 * m + 2], a2);
        a3 = fmaf(xv.w, w2[4 * m + 3], a3);
    }
    g_y[i * CH + lane] = (a0 + a1) + (a2 + a3);
}

// ---------------------------------------------------------------------------
// conv2 (+ fused global max pool)
// ---------------------------------------------------------------------------
__global__ __launch_bounds__(256) void conv2_kernel(
    const float* __restrict__ pos, const float* __restrict__ nrm,
    const float* __restrict__ w2a,
    const float* __restrict__ w2b, const float* __restrict__ b2b)
{
    __shared__ float4 sf[8][20];
    __shared__ int    si[8][20];
    __shared__ float  sh[8][17][32];
    __shared__ float  red[8][32];
    int warp = threadIdx.x >> 5;
    int lane = threadIdx.x & 31;
    int i    = blockIdx.x * 8 + warp;

    float wa32 = w2a[32 * 32 + lane], wa33 = w2a[33 * 32 + lane];
    float wa34 = w2a[34 * 32 + lane], wa35 = w2a[35 * 32 + lane];
    float wb[32];
#pragma unroll
    for (int k = 0; k < 32; k++) wb[k] = w2b[k * 32 + lane];
    float bb = b2b[lane];

    float pix = pos[3 * i + 0], piy = pos[3 * i + 1], piz = pos[3 * i + 2];
    float nix = nrm[3 * i + 0], niy = nrm[3 * i + 1], niz = nrm[3 * i + 2];

    int j = (lane < KNN) ? g_knn[i * KNN + lane] : i;
    float pjx = pos[3 * j + 0], pjy = pos[3 * j + 1], pjz = pos[3 * j + 2];
    float njx = nrm[3 * j + 0], njy = nrm[3 * j + 1], njz = nrm[3 * j + 2];

    float px = pjx - pix, py = pjy - piy, pz = pjz - piz;
    float f0 = safe_norm3(px, py, pz);
    float f1 = angle3(nix, niy, niz, px, py, pz);
    float f2 = angle3(njx, njy, njz, px, py, pz);
    float f3 = angle3(nix, niy, niz, njx, njy, njz);
    if (lane < 17) { sf[warp][lane] = make_float4(f0, f1, f2, f3); si[warp][lane] = j; }
    __syncwarp();

    float yv[17];
#pragma unroll
    for (int e = 0; e < 17; e++)
        yv[e] = g_y[si[warp][e] * CH + lane];

#pragma unroll
    for (int e = 0; e < 17; e++) {
        float4 f = sf[warp][e];
        float h = yv[e];
        h = fmaf(f.x, wa32, h); h = fmaf(f.y, wa33, h);
        h = fmaf(f.z, wa34, h); h = fmaf(f.w, wa35, h);
        sh[warp][e][lane] = fmaxf(h, 0.f);
    }
    __syncwarp();

    float best = -CUDART_INF_F;
    for (int e = 0; e < 17; e++) {
        float o0 = bb, o1 = 0.f, o2 = 0.f, o3 = 0.f;
        const float4* hv4 = (const float4*)sh[warp][e];
#pragma unroll
        for (int m = 0; m < 8; m++) {
            float4 hv = hv4[m];
            o0 = fmaf(hv.x, wb[4 * m + 0], o0);
            o1 = fmaf(hv.y, wb[4 * m + 1], o1);
            o2 = fmaf(hv.z, wb[4 * m + 2], o2);
            o3 = fmaf(hv.w, wb[4 * m + 3], o3);
        }
        best = fmaxf(best, (o0 + o1) + (o2 + o3));
    }
    red[warp][lane] = fmaxf(best, 0.f);
    __syncthreads();

    if (warp == 0) {
        float m = red[0][lane];
#pragma unroll
        for (int r = 1; r < 8; r++) m = fmaxf(m, red[r][lane]);
        int b = (blockIdx.x * 8) >> 12;
        atomicMax((int*)&g_pool[b * CH + lane], __float_as_int(m));
    }
}

__global__ void fc_kernel(const float* __restrict__ wc,
                          const float* __restrict__ bc,
                          float* __restrict__ out) {
    int t = threadIdx.x;
    if (t < NB * NCLS) {
        int b = t / NCLS, o = t % NCLS;
        float acc = bc[o];
#pragma unroll
        for (int c = 0; c < CH; c++)
            acc = fmaf(g_pool[b * CH + c], wc[c * NCLS + o], acc);
        out[t] = acc;
    }
}

extern "C" void kernel_launch(void* const* d_in, const int* in_sizes, int n_in,
                              void* d_out, int out_size) {
    const float* pos = (const float*)d_in[0];
    const float* nrm = (const float*)d_in[1];
    const float* w1a = (const float*)d_in[3];
    const float* b1a = (const float*)d_in[4];
    const float* w1b = (const float*)d_in[5];
    const float* b1b = (const float*)d_in[6];
    const float* w2a = (const float*)d_in[7];
    const float* b2a = (const float*)d_in[8];
    const float* w2b = (const float*)d_in[9];
    const float* b2b = (const float*)d_in[10];
    const float* wc  = (const float*)d_in[11];
    const float* bc  = (const float*)d_in[12];
    float* out = (float*)d_out;

    prep_kernel<<<MPTS / 512, 256>>>(pos, 0);
    prep_kernel<<<MPTS / 512, 256>>>(pos, MPTS / 2);
    pool_init_kernel<<<1, 256>>>();
    knn_kernel<<<MPTS / 16, 256>>>();                 // 4th launch (ncu sample)
    conv1_kernel<<<MPTS / 8, 256>>>(pos, nrm, w1a, b1a, w1b, b1b, w2a, b2a);
    conv2_kernel<<<MPTS / 8, 256>>>(pos, nrm, w2a, w2b, b2b);
    fc_kernel<<<1, 320>>>(wc, bc, out);
}

// round 9
// speedup vs baseline: 1.1815x; 1.1666x over previous
#include <cuda_runtime.h>
#include <math_constants.h>

#define NB 8
#define NPTS 4096
#define KNN 16
#define MPTS (NB * NPTS)
#define CH 32
#define NCLS 40

__device__ int    g_knn[MPTS * KNN];
__device__ float  g_y[MPTS * CH];
__device__ float4 g_feat[MPTS * 17];   // PPF per edge, computed once in conv1
__device__ float  g_pool[NB * CH];

__device__ __forceinline__ float safe_norm3(float x, float y, float z) {
    float s = x * x + y * y + z * z;
    return s > 0.f ? sqrtf(s) : 0.f;
}

__device__ __forceinline__ float angle3(float ax, float ay, float az,
                                        float bx, float by, float bz) {
    float cx = ay * bz - az * by;
    float cy = az * bx - ax * bz;
    float cz = ax * by - ay * bx;
    float cn = safe_norm3(cx, cy, cz);
    float d  = ax * bx + ay * by + az * bz;
    bool ok = (cn > 0.f) || (d != 0.f);
    return ok ? atan2f(cn, d) : 0.f;
}

__global__ void pool_init_kernel() {
    int t = threadIdx.x;
    if (t < NB * CH) g_pool[t] = 0.f;
}

// ---------------------------------------------------------------------------
// kNN warp-select (proven R6 structure): 2 queries/warp; every lane evaluates
// a DISTINCT candidate against BOTH queries. q0's sorted top-16 in lanes
// 0..15, q1's in lanes 16..31; one insert round serves both queries.
// prep is inlined: the tile fill reads pos directly and computes |p|^2.
// ---------------------------------------------------------------------------
__global__ __launch_bounds__(256) void knn_kernel(const float* __restrict__ pos) {
    const unsigned FULL = 0xFFFFFFFFu;
    const float INF = CUDART_INF_F;
    int lane = threadIdx.x & 31;
    int warp = threadIdx.x >> 5;
    int half = lane >> 4;
    int lh   = lane & 15;
    int hsh  = half << 4;

    int qbase = blockIdx.x * 16;
    int q0    = qbase + warp * 2;          // even
    int batch = blockIdx.x >> 8;
    int q0l   = q0 & (NPTS - 1);
    int q1l   = q0l + 1;                   // same 32-block as q0l (q0l even)
    int selfb = q0l & ~31;

    float p0x = pos[3 * q0 + 0], p0y = pos[3 * q0 + 1], p0z = pos[3 * q0 + 2];
    float p1x = pos[3 * q0 + 3], p1y = pos[3 * q0 + 4], p1z = pos[3 * q0 + 5];
    float m2x0 = -2.f * p0x, m2y0 = -2.f * p0y, m2z0 = -2.f * p0z;
    float m2x1 = -2.f * p1x, m2y1 = -2.f * p1y, m2z1 = -2.f * p1z;

    float L  = INF;      // my slot of my query's sorted top-16 (shifted d2)
    int   LI = 0;
    float tp0 = INF;     // q0's running 16th best
    float tp1 = INF;

    const float* bp = pos + (size_t)batch * NPTS * 3;
    __shared__ float4 tile[1024];

    for (int t = 0; t < NPTS; t += 1024) {
        __syncthreads();
#pragma unroll
        for (int u = 0; u < 4; u++) {
            int p = t + threadIdx.x + u * 256;
            float cx = bp[3 * p + 0], cy = bp[3 * p + 1], cz = bp[3 * p + 2];
            tile[threadIdx.x + u * 256] =
                make_float4(cx, cy, cz, cx * cx + cy * cy + cz * cz);
        }
        __syncthreads();

#pragma unroll 4
        for (int s = 0; s < 32; s++) {
            int base = t + s * 32;                 // batch-local candidate base
            float4 c = tile[s * 32 + lane];
            float d0 = fmaf(c.x, m2x0, fmaf(c.y, m2y0, fmaf(c.z, m2z0, c.w)));
            float d1 = fmaf(c.x, m2x1, fmaf(c.y, m2y1, fmaf(c.z, m2z1, c.w)));
            if (base == selfb) {                   // rare uniform branch
                int cl = base + lane;
                if (cl == q0l) d0 = INF;
                if (cl == q1l) d1 = INF;
            }
            unsigned bal0 = __ballot_sync(FULL, d0 < tp0);
            unsigned bal1 = __ballot_sync(FULL, d1 < tp1);
            while (bal0 | bal1) {
                int s0 = __ffs(bal0) - 1;          // -1 when empty
                int s1 = __ffs(bal1) - 1;
                float v0 = __shfl_sync(FULL, d0, bal0 ? s0 : 0);
                float v1 = __shfl_sync(FULL, d1, bal1 ? s1 : 0);
                float v;
                int   vi;
                if (half) { v = bal1 ? v1 : INF; vi = base + s1; }
                else      { v = bal0 ? v0 : INF; vi = base + s0; }
                unsigned ble = __ballot_sync(FULL, L <= v);
                int pos_ = __popc((ble >> hsh) & 0xFFFFu);
                float Lup = __shfl_up_sync(FULL, L, 1);
                int  LIup = __shfl_up_sync(FULL, LI, 1);
                if (lh == pos_)      { L = v;   LI = vi;   }
                else if (lh > pos_)  { L = Lup; LI = LIup; }
                tp0 = __shfl_sync(FULL, L, 15);
                tp1 = __shfl_sync(FULL, L, 31);
                bal0 &= bal0 - 1;                  // clear lowest (no-op at 0)
                bal1 &= bal1 - 1;
            }
        }
    }
    int q = q0 + half;
    g_knn[q * KNN + lh] = batch * NPTS + LI;
}

// ---------------------------------------------------------------------------
// conv1 (+ fused y = w2a[0:32]^T x1 + b2a; also materializes PPF feats)
// ---------------------------------------------------------------------------
__global__ __launch_bounds__(256) void conv1_kernel(
    const float* __restrict__ pos, const float* __restrict__ nrm,
    const float* __restrict__ w1a, const float* __restrict__ b1a,
    const float* __restrict__ w1b, const float* __restrict__ b1b,
    const float* __restrict__ w2a, const float* __restrict__ b2a)
{
    __shared__ float4 sf[8][20];
    __shared__ float  sh[8][17][32];
    int warp = threadIdx.x >> 5;
    int lane = threadIdx.x & 31;
    int i    = blockIdx.x * 8 + warp;

    float wa0 = w1a[0 * 32 + lane], wa1 = w1a[1 * 32 + lane];
    float wa2 = w1a[2 * 32 + lane], wa3 = w1a[3 * 32 + lane];
    float ba  = b1a[lane];
    float wb[32];
#pragma unroll
    for (int k = 0; k < 32; k++) wb[k] = w1b[k * 32 + lane];
    float bb = b1b[lane];

    float pix = pos[3 * i + 0], piy = pos[3 * i + 1], piz = pos[3 * i + 2];
    float nix = nrm[3 * i + 0], niy = nrm[3 * i + 1], niz = nrm[3 * i + 2];

    int j = (lane < KNN) ? g_knn[i * KNN + lane] : i;   // lane16 = self loop
    float pjx = pos[3 * j + 0], pjy = pos[3 * j + 1], pjz = pos[3 * j + 2];
    float njx = nrm[3 * j + 0], njy = nrm[3 * j + 1], njz = nrm[3 * j + 2];

    float px = pjx - pix, py = pjy - piy, pz = pjz - piz;
    float f0 = safe_norm3(px, py, pz);
    float f1 = angle3(nix, niy, niz, px, py, pz);
    float f2 = angle3(njx, njy, njz, px, py, pz);
    float f3 = angle3(nix, niy, niz, njx, njy, njz);
    if (lane < 17) {
        float4 f = make_float4(f0, f1, f2, f3);
        sf[warp][lane] = f;
        g_feat[i * 17 + lane] = f;      // reuse in conv2
    }
    __syncwarp();

    for (int e = 0; e < 17; e++) {
        float4 f = sf[warp][e];
        float h = ba;
        h = fmaf(f.x, wa0, h); h = fmaf(f.y, wa1, h);
        h = fmaf(f.z, wa2, h); h = fmaf(f.w, wa3, h);
        sh[warp][e][lane] = fmaxf(h, 0.f);
    }
    __syncwarp();

    float best = -CUDART_INF_F;
    for (int e = 0; e < 17; e++) {
        float o0 = bb, o1 = 0.f, o2 = 0.f, o3 = 0.f;
        const float4* hv4 = (const float4*)sh[warp][e];
#pragma unroll
        for (int m = 0; m < 8; m++) {
            float4 hv = hv4[m];
            o0 = fmaf(hv.x, wb[4 * m + 0], o0);
            o1 = fmaf(hv.y, wb[4 * m + 1], o1);
            o2 = fmaf(hv.z, wb[4 * m + 2], o2);
            o3 = fmaf(hv.w, wb[4 * m + 3], o3);
        }
        best = fmaxf(best, (o0 + o1) + (o2 + o3));
    }
    float x1v = fmaxf(best, 0.f);

    sh[warp][0][lane] = x1v;
    __syncwarp();
    float w2[32];
#pragma unroll
    for (int k = 0; k < 32; k++) w2[k] = w2a[k * 32 + lane];
    float a0 = b2a[lane], a1 = 0.f, a2 = 0.f, a3 = 0.f;
    const float4* xv4 = (const float4*)sh[warp][0];
#pragma unroll
    for (int m = 0; m < 8; m++) {
        float4 xv = xv4[m];
        a0 = fmaf(xv.x, w2[4 * m + 0], a0);
        a1 = fmaf(xv.y, w2[4 * m + 1], a1);
        a2 = fmaf(xv.z, w2[4 * m + 2], a2);
        a3 = fmaf(xv.w, w2[4 * m + 3], a3);
    }
    g_y[i * CH + lane] = (a0 + a1) + (a2 + a3);
}

// ---------------------------------------------------------------------------
// conv2 (+ fused global max pool): reads precomputed PPF feats from g_feat.
// ---------------------------------------------------------------------------
__global__ __launch_bounds__(256) void conv2_kernel(
    const float* __restrict__ w2a,
    const float* __restrict__ w2b, const float* __restrict__ b2b)
{
    __shared__ int   si[8][20];
    __shared__ float sh[8][17][32];
    __shared__ float red[8][32];
    int warp = threadIdx.x >> 5;
    int lane = threadIdx.x & 31;
    int i    = blockIdx.x * 8 + warp;

    float wa32 = w2a[32 * 32 + lane], wa33 = w2a[33 * 32 + lane];
    float wa34 = w2a[34 * 32 + lane], wa35 = w2a[35 * 32 + lane];
    float wb[32];
#pragma unroll
    for (int k = 0; k < 32; k++) wb[k] = w2b[k * 32 + lane];
    float bb = b2b[lane];

    int j = (lane < KNN) ? g_knn[i * KNN + lane] : i;
    if (lane < 17) si[warp][lane] = j;
    __syncwarp();

    float yv[17];
#pragma unroll
    for (int e = 0; e < 17; e++)
        yv[e] = g_y[si[warp][e] * CH + lane];

#pragma unroll
    for (int e = 0; e < 17; e++) {
        float4 f = g_feat[i * 17 + e];     // broadcast load, L1/L2-cached
        float h = yv[e];
        h = fmaf(f.x, wa32, h); h = fmaf(f.y, wa33, h);
        h = fmaf(f.z, wa34, h); h = fmaf(f.w, wa35, h);
        sh[warp][e][lane] = fmaxf(h, 0.f);
    }
    __syncwarp();

    float best = -CUDART_INF_F;
    for (int e = 0; e < 17; e++) {
        float o0 = bb, o1 = 0.f, o2 = 0.f, o3 = 0.f;
        const float4* hv4 = (const float4*)sh[warp][e];
#pragma unroll
        for (int m = 0; m < 8; m++) {
            float4 hv = hv4[m];
            o0 = fmaf(hv.x, wb[4 * m + 0], o0);
            o1 = fmaf(hv.y, wb[4 * m + 1], o1);
            o2 = fmaf(hv.z, wb[4 * m + 2], o2);
            o3 = fmaf(hv.w, wb[4 * m + 3], o3);
        }
        best = fmaxf(best, (o0 + o1) + (o2 + o3));
    }
    red[warp][lane] = fmaxf(best, 0.f);
    __syncthreads();

    if (warp == 0) {
        float m = red[0][lane];
#pragma unroll
        for (int r = 1; r < 8; r++) m = fmaxf(m, red[r][lane]);
        int b = (blockIdx.x * 8) >> 12;
        atomicMax((int*)&g_pool[b * CH + lane], __float_as_int(m));
    }
}

__global__ void fc_kernel(const float* __restrict__ wc,
                          const float* __restrict__ bc,
                          float* __restrict__ out) {
    int t = threadIdx.x;
    if (t < NB * NCLS) {
        int b = t / NCLS, o = t % NCLS;
        float acc = bc[o];
#pragma unroll
        for (int c = 0; c < CH; c++)
            acc = fmaf(g_pool[b * CH + c], wc[c * NCLS + o], acc);
        out[t] = acc;
    }
}

extern "C" void kernel_launch(void* const* d_in, const int* in_sizes, int n_in,
                              void* d_out, int out_size) {
    const float* pos = (const float*)d_in[0];
    const float* nrm = (const float*)d_in[1];
    const float* w1a = (const float*)d_in[3];
    const float* b1a = (const float*)d_in[4];
    const float* w1b = (const float*)d_in[5];
    const float* b1b = (const float*)d_in[6];
    const float* w2a = (const float*)d_in[7];
    const float* b2a = (const float*)d_in[8];
    const float* w2b = (const float*)d_in[9];
    const float* b2b = (const float*)d_in[10];
    const float* wc  = (const float*)d_in[11];
    const float* bc  = (const float*)d_in[12];
    float* out = (float*)d_out;

    knn_kernel<<<MPTS / 16, 256>>>(pos);                               // 1
    conv1_kernel<<<MPTS / 8, 256>>>(pos, nrm, w1a, b1a, w1b, b1b, w2a, b2a); // 2
    pool_init_kernel<<<1, 256>>>();                                    // 3
    conv2_kernel<<<MPTS / 8, 256>>>(w2a, w2b, b2b);                    // 4 (ncu)
    fc_kernel<<<1, 320>>>(wc, bc, out);                                // 5
}